// round 14
// baseline (speedup 1.0000x reference)
#include <cuda_runtime.h>
#include <math.h>

// Problem dims
#define BB 8
#define TT 250
#define SS 64
#define NSAMP 64000
#define NREG 251            // head(128) + 249 full segments(256) + tail(128)
#define NBLK  (BB*NREG)     // 2008 blocks
#define NPREP (BB*SS)       // 512 prep units (one per (b,s))

// Scratch (no cudaMalloc allowed)
__device__ float4 g_p4[BB*NREG*SS];   // {w' (midpoint omega), q, base' (mod 2pi), a0'}
__device__ float  g_da[BB*NREG*SS];   // da' (amp slope per k')
__device__ int          g_ready;      // prep-units-done counter (self-resetting)
__device__ unsigned int g_fin;        // blocks-finished counter (self-resetting)

// ===========================================================================
// double-single (two-float) arithmetic on the fp32 pipe (exact-FMA based).
// ===========================================================================
struct ff { float h, l; };

__device__ __forceinline__ ff ff_two_prod(float a, float b) {
    float p = a * b;
    float e = fmaf(a, b, -p);
    return {p, e};
}
__device__ __forceinline__ ff ff_add(ff a, ff b) {
    float s  = a.h + b.h;
    float d  = s - a.h;
    float e  = (a.h - (s - d)) + (b.h - d);
    e += a.l + b.l;
    float h = s + e;
    float l = (s - h) + e;
    return {h, l};
}
__device__ __forceinline__ ff ff_neg(ff a) { return {-a.h, -a.l}; }
__device__ __forceinline__ ff ff_mul(ff a, ff z) {
    float p = a.h * z.h;
    float e = fmaf(a.h, z.h, -p);
    e = fmaf(a.h, z.l, e);
    e = fmaf(a.l, z.h, e);
    float h = p + e;
    float l = (p - h) + e;
    return {h, l};
}
__device__ __forceinline__ ff ff_cadd(float ch, float cl, ff p) {
    float s = ch + p.h;
    float e = (ch - s) + p.h;
    e += p.l + cl;
    float h = s + e;
    float l = (s - h) + e;
    return {h, l};
}
__device__ __forceinline__ ff ff_scale(ff a, float k) {   // k power of 2
    return {a.h * k, a.l * k};
}
__device__ __forceinline__ ff ff_mulf(ff a, float k) {    // general float k
    float p = k * a.h;
    float e = fmaf(k, a.h, -p);
    e = fmaf(k, a.l, e);
    float h = p + e;
    float l = (p - h) + e;
    return {h, l};
}

#define DFH(d) ((float)(d))
#define DFL(d) ((float)((d) - (double)(float)(d)))

// exp(z), |z| <= 0.3466, as two-float.  Taylor deg 11 (tail fp32).
__device__ __forceinline__ ff ff_exp_core(float zh, float zl) {
    float t;
    t = fmaf(zh, 2.5052108385441718775e-8f, 2.7557319223985890653e-7f);
    t = fmaf(zh, t, 2.7557319223985890653e-6f);
    t = fmaf(zh, t, 2.4801587301587301588e-5f);
    t = fmaf(zh, t, 1.9841269841269841270e-4f);
    ff P = {t, 0.0f};
    ff z = {zh, zl};
    P = ff_cadd(DFH(1.0/720.0), DFL(1.0/720.0), ff_mul(P, z));
    P = ff_cadd(DFH(1.0/120.0), DFL(1.0/120.0), ff_mul(P, z));
    P = ff_cadd(DFH(1.0/24.0),  DFL(1.0/24.0),  ff_mul(P, z));
    P = ff_cadd(DFH(1.0/6.0),   DFL(1.0/6.0),   ff_mul(P, z));
    P = ff_cadd(0.5f, 0.0f, ff_mul(P, z));
    P = ff_cadd(1.0f, 0.0f, ff_mul(P, z));
    P = ff_cadd(1.0f, 0.0f, ff_mul(P, z));
    return P;
}

// sigmoid(y) correctly rounded to f32 (err ~1e-14 before final rounding)
__device__ __forceinline__ float sigmoid_rn(float y) {
    float z = fminf(fmaxf(-y, -30.0f), 30.0f);
    float n = rintf(z * 1.4426950408889634f);
    float rh = fmaf(-n, 0.693359375f, z);       // exact (9-bit constant)
    const double CRd = 0.69314718055994530942 - 0.693359375;
    ff p = ff_two_prod(-n, DFH(CRd));
    float s  = rh + p.h;
    float d  = s - rh;
    float e  = (rh - (s - d)) + (p.h - d);
    e += p.l + (-n) * DFL(CRd);
    float z2h = s + e;
    float z2l = (s - z2h) + e;
    ff E = ff_exp_core(z2h, z2l);
    int ni = (int)n;
    float sc = __int_as_float((ni + 127) << 23);
    float th = E.h * sc, tl = E.l * sc;
    float s2  = 1.0f + th;
    float d2  = s2 - 1.0f;
    float sl2 = (1.0f - (s2 - d2)) + (th - d2);
    sl2 += tl;
    float q0 = 1.0f / s2;
    float r  = fmaf(-q0, s2, 1.0f);
    r = fmaf(-q0, sl2, r);
    return fmaf(q0, r, q0);
}

// 2^e correctly rounded to f32 (e in ~(-6, 5))
__device__ __forceinline__ float exp2_rn(float e) {
    float n = rintf(e);
    float r = e - n;                     // exact
    const double LN2 = 0.69314718055994530942;
    float zh = r * DFH(LN2);
    float ze = fmaf(r, DFH(LN2), -zh);
    float zl = fmaf(r, DFL(LN2), ze);
    ff E = ff_exp_core(zh, zl);
    float pw = E.h + E.l;
    return pw * __int_as_float(((int)n + 127) << 23);
}

// ---------------------------------------------------------------------------
// Packed f32x2 helpers (FFMA2 — only reachable via PTX fma.rn.f32x2)
// ---------------------------------------------------------------------------
__device__ __forceinline__ unsigned long long pk2(float lo, float hi) {
    unsigned long long p;
    asm("mov.b64 %0, {%1, %2};" : "=l"(p) : "f"(lo), "f"(hi));
    return p;
}
__device__ __forceinline__ void upk2(unsigned long long p, float& lo, float& hi) {
    asm("mov.b64 {%0, %1}, %2;" : "=f"(lo), "=f"(hi) : "l"(p));
}
__device__ __forceinline__ unsigned long long fma2(unsigned long long a,
                                                   unsigned long long b,
                                                   unsigned long long c) {
    unsigned long long d;
    asm("fma.rn.f32x2 %0, %1, %2, %3;" : "=l"(d) : "l"(a), "l"(b), "l"(c));
    return d;
}

// ===========================================================================
// Fused single-wave kernel.
//   Blocks 0..NPREP-1 first run "prep" for (b,s) = (blk/64, blk%64):
//     control math (df64 sigmoid/exp2, f32 roundings matching reference),
//     df64 scan of segment phase increments, per-region coefficients.
//   All blocks then spin on g_ready==NPREP (all co-resident: one wave is
//   guaranteed by __launch_bounds__(64,16): 148*16=2368 >= 2008 blocks)
//   and run the synth loop (MUFU floor, best-measured structure).
//
// jax.image.resize 'linear' (x256): coord(i) = (i+0.5)/256 - 0.5.
//   region 0   : samples [0,128)          constant f[0]
//   region r   : samples [256r-128,+256)  lerp f[r-1]->f[r], frac=(2i+1)/512
//   region 250 : samples [63872,64000)    constant f[249]
// phi(k) = P_base + k*om_prev + k^2*q, recentred at kc = len/2 (k' = k-kc).
// amp(k') = a0' + k'*da'.
// ===========================================================================
__global__ void __launch_bounds__(64, 16)
fused_kernel(float* __restrict__ out,
             const float* __restrict__ amps_in,
             const float* __restrict__ freqs_in) {
    __shared__ __align__(16) char smraw[3072];

    int blk = blockIdx.x;
    int tid = threadIdx.x;

    // ---------------- Phase A: prep (blocks 0..511) ----------------
    if (blk < NPREP) {
        float2* s_om = (float2*)smraw;             // [250] : 2000 B
        float*  s_a  = (float*)(smraw + 2000);     // [250] : 1000 B
        float2* s_ws = (float2*)(smraw + 3000);    // [2]   : warp sums

        int b = blk >> 6, s = blk & 63;

        // control-rate math: 4 points per thread
        for (int j = tid; j < TT; j += 64) {
            int gidx = (b*TT + j)*SS + s;

            float uf   = sigmoid_rn(freqs_in[gidx]);
            const float MIDI_MAX = 119.21309485364912f; // np.float32(hz_to_midi(8000))
            float midi = uf * MIDI_MAX;
            float e    = (midi - 69.0f) / 12.0f;
            float pw   = exp2_rn(e);
            float freq = 440.0f * pw;

            float x  = amps_in[gidx];
            float sf = 1.0f / (1.0f + __expf(-x));
            float a  = 2.0f * __powf(sf, 2.3025850929940457f) + 1e-7f;
            if (freq >= 8000.0f) a = 0.0f;   // remove_above_nyquist

            const float CF = 3.9269908169872414e-4f;   // fp32(2*pi/16000)
            ff om = ff_two_prod(CF, freq);             // exact product
            s_om[j] = make_float2(om.h, om.l);
            s_a[j]  = a;
        }
        __syncthreads();

        // thread t owns e_{4t+1..4t+4}:
        //   e_1 = 128*om_0; e_j = 128*(om_{j-2}+om_{j-1}), j<=250; else 0
        ff cc[4];
        ff run = {0.0f, 0.0f};
        #pragma unroll
        for (int k = 0; k < 4; k++) {
            int j = 4*tid + 1 + k;
            ff e = {0.0f, 0.0f};
            if (j == 1) {
                e = ff_scale({s_om[0].x, s_om[0].y}, 128.0f);
            } else if (j <= 250) {
                e = ff_scale(ff_add({s_om[j-2].x, s_om[j-2].y},
                                    {s_om[j-1].x, s_om[j-1].y}), 128.0f);
            }
            run = ff_add(run, e);
            cc[k] = run;
        }
        ff S = cc[3];
        ff C = S;
        int lane = tid & 31, warp = tid >> 5;
        #pragma unroll
        for (int d = 1; d < 32; d <<= 1) {
            float oh = __shfl_up_sync(0xffffffffu, C.h, d);
            float ol = __shfl_up_sync(0xffffffffu, C.l, d);
            if (lane >= d) C = ff_add(C, {oh, ol});
        }
        if (lane == 31) s_ws[warp] = make_float2(C.h, C.l);
        __syncthreads();
        if (warp == 1) C = ff_add(C, {s_ws[0].x, s_ws[0].y});
        ff E = ff_add(C, ff_neg(S));   // exclusive prefix: through e_{4t}

        // outputs for regions rr = 4t .. 4t+3
        #pragma unroll
        for (int k = 0; k < 4; k++) {
            int rr = 4*tid + k;
            if (rr <= 250) {
                ff P = (k == 0) ? E : ff_add(E, cc[k-1]);
                ff base_df;
                float w, q, a0p, dap;
                if (rr == 0) {
                    ff om0 = {s_om[0].x, s_om[0].y};
                    w = om0.h + om0.l; q = 0.0f;
                    base_df = ff_scale(om0, 64.0f);
                    a0p = s_a[0]; dap = 0.0f;
                } else if (rr == 250) {
                    ff omN = {s_om[249].x, s_om[249].y};
                    w = omN.h + omN.l; q = 0.0f;
                    base_df = ff_add(P, ff_scale(omN, 64.0f));
                    a0p = s_a[249]; dap = 0.0f;
                } else {
                    ff omp = {s_om[rr-1].x, s_om[rr-1].y};
                    ff om  = {s_om[rr].x,   s_om[rr].y};
                    ff qd  = ff_add(om, ff_neg(omp));
                    q = (qd.h + qd.l) * (1.0f/512.0f);
                    ff wv = ff_add(omp, om);
                    w = 0.5f * (wv.h + wv.l);
                    base_df = ff_add(P, ff_add(ff_mulf(omp, 96.0f), ff_scale(om, 32.0f)));
                    float a0 = s_a[rr-1], da = s_a[rr] - s_a[rr-1];
                    a0p = fmaf(da, 255.0f/512.0f, a0);  // amp at k'=0 (i=127)
                    dap = da * (1.0f/256.0f);           // amp slope per k'
                }
                const double T2P = 6.2831853071795864769;
                float nn = rintf(base_df.h * 0.15915494309189535f);
                ff m = ff_two_prod(nn, DFH(T2P));
                m.l = fmaf(nn, DFL(T2P), m.l);
                ff bred = ff_add(base_df, ff_neg(m));
                float base = bred.h + bred.l;

                int idx = (b*NREG + rr)*SS + s;
                g_p4[idx] = make_float4(w, q, base, a0p);
                g_da[idx] = dap;
            }
        }
        __threadfence();
        __syncthreads();
        if (tid == 0) atomicAdd(&g_ready, 1);
    }

    // ---------------- Wave barrier: wait for all prep units ----------------
    if (tid == 0) {
        while (*(volatile int*)&g_ready < NPREP) __nanosleep(64);
        __threadfence();
    }
    __syncthreads();

    // ---------------- Phase B: synth (all 2008 blocks) ----------------
    float (*sp)[12] = (float (*)[12])smraw;  // overwrites prep smem (consumed)

    int b   = blk / NREG;
    int r   = blk % NREG;

    int n0, half;
    if (r == 0)        { n0 = 0;         half = 64;  }
    else if (r == 250) { n0 = 63872;     half = 64;  }
    else               { n0 = 256*r-128; half = 128; }
    bool full = (half == 128);

    unsigned long long kpA = pk2((float)(tid + 1 - half), (float)(tid + 1));
    unsigned long long kpB = pk2((float)(tid + 65 - half), (float)(tid + 65));
    float* ob = out + (size_t)b*NSAMP + n0;

    {
        int idx = (b*NREG + r)*SS + tid;
        float4 v = g_p4[idx];
        float  d = g_da[idx];
        sp[tid][0] = v.x; sp[tid][1] = v.x;
        sp[tid][2] = v.y; sp[tid][3] = v.y;
        sp[tid][4] = v.z; sp[tid][5] = v.z;
        sp[tid][6] = v.w; sp[tid][7] = v.w;
        sp[tid][8] = d;   sp[tid][9] = d;
    }
    __syncthreads();

    unsigned long long accA = 0ull, accB = 0ull;

    #pragma unroll
    for (int si = 0; si < SS; si++) {
        const unsigned long long* q8 = (const unsigned long long*)sp[si];
        unsigned long long ww = q8[0], qq = q8[1], bb = q8[2],
                           aa = q8[3], dd = q8[4];

        unsigned long long hA = fma2(kpA, qq, ww);
        unsigned long long tA = fma2(kpA, hA, bb);
        unsigned long long hB = fma2(kpB, qq, ww);
        unsigned long long tB = fma2(kpB, hB, bb);
        float t0, t1, t2, t3;
        upk2(tA, t0, t1);
        upk2(tB, t2, t3);
        float s0 = __sinf(t0);
        float s1 = __sinf(t1);
        float s2 = __sinf(t2);
        float s3 = __sinf(t3);
        unsigned long long amA = fma2(kpA, dd, aa);
        unsigned long long amB = fma2(kpB, dd, aa);
        accA = fma2(amA, pk2(s0, s1), accA);
        accB = fma2(amB, pk2(s2, s3), accB);
    }

    float oA0, oA1, oB0, oB1;
    upk2(accA, oA0, oA1);
    upk2(accB, oB0, oB1);
    ob[tid]        = oA0;
    ob[tid + half] = oA1;
    if (full) {
        ob[tid + 64]        = oB0;
        ob[tid + 64 + half] = oB1;
    }

    // ---------------- Counter reset by last finishing block ----------------
    if (tid == 0) {
        __threadfence();
        unsigned f = atomicAdd(&g_fin, 1u);
        if (f == (unsigned)(NBLK - 1)) {
            g_ready = 0;
            __threadfence();
            g_fin = 0u;
        }
    }
}

// ---------------------------------------------------------------------------
extern "C" void kernel_launch(void* const* d_in, const int* in_sizes, int n_in,
                              void* d_out, int out_size) {
    const float* amplitudes  = (const float*)d_in[0];
    const float* frequencies = (const float*)d_in[1];
    float* out = (float*)d_out;
    (void)in_sizes; (void)n_in; (void)out_size;

    fused_kernel<<<NBLK, 64>>>(out, amplitudes, frequencies);
}

// round 15
// speedup vs baseline: 1.4157x; 1.4157x over previous
#include <cuda_runtime.h>
#include <math.h>

// Problem dims
#define BB 8
#define TT 250
#define SS 64
#define NSAMP 64000
#define NREG 251          // head(128) + 249 full segments(256) + tail(128)

// Scratch (no cudaMalloc allowed)
__device__ float4 g_p4[BB*NREG*SS];   // {w' (midpoint omega), q, base' (mod 2pi), a0}
__device__ float  g_da[BB*NREG*SS];   // amp delta

// ===========================================================================
// double-single (two-float) arithmetic on the fp32 pipe (exact-FMA based).
// ===========================================================================
struct ff { float h, l; };

__device__ __forceinline__ ff ff_two_prod(float a, float b) {
    float p = a * b;
    float e = fmaf(a, b, -p);
    return {p, e};
}
__device__ __forceinline__ ff ff_add(ff a, ff b) {
    float s  = a.h + b.h;
    float d  = s - a.h;
    float e  = (a.h - (s - d)) + (b.h - d);
    e += a.l + b.l;
    float h = s + e;
    float l = (s - h) + e;
    return {h, l};
}
__device__ __forceinline__ ff ff_neg(ff a) { return {-a.h, -a.l}; }
__device__ __forceinline__ ff ff_mul(ff a, ff z) {
    float p = a.h * z.h;
    float e = fmaf(a.h, z.h, -p);
    e = fmaf(a.h, z.l, e);
    e = fmaf(a.l, z.h, e);
    float h = p + e;
    float l = (p - h) + e;
    return {h, l};
}
__device__ __forceinline__ ff ff_cadd(float ch, float cl, ff p) {
    float s = ch + p.h;
    float e = (ch - s) + p.h;
    e += p.l + cl;
    float h = s + e;
    float l = (s - h) + e;
    return {h, l};
}
__device__ __forceinline__ ff ff_scale(ff a, float k) {   // k power of 2
    return {a.h * k, a.l * k};
}
__device__ __forceinline__ ff ff_mulf(ff a, float k) {    // general float k
    float p = k * a.h;
    float e = fmaf(k, a.h, -p);
    e = fmaf(k, a.l, e);
    float h = p + e;
    float l = (p - h) + e;
    return {h, l};
}

#define DFH(d) ((float)(d))
#define DFL(d) ((float)((d) - (double)(float)(d)))

// exp(z), |z| <= 0.3466, as two-float.  Taylor deg 11 (tail fp32).
__device__ __forceinline__ ff ff_exp_core(float zh, float zl) {
    float t;
    t = fmaf(zh, 2.5052108385441718775e-8f, 2.7557319223985890653e-7f);
    t = fmaf(zh, t, 2.7557319223985890653e-6f);
    t = fmaf(zh, t, 2.4801587301587301588e-5f);
    t = fmaf(zh, t, 1.9841269841269841270e-4f);
    ff P = {t, 0.0f};
    ff z = {zh, zl};
    P = ff_cadd(DFH(1.0/720.0), DFL(1.0/720.0), ff_mul(P, z));
    P = ff_cadd(DFH(1.0/120.0), DFL(1.0/120.0), ff_mul(P, z));
    P = ff_cadd(DFH(1.0/24.0),  DFL(1.0/24.0),  ff_mul(P, z));
    P = ff_cadd(DFH(1.0/6.0),   DFL(1.0/6.0),   ff_mul(P, z));
    P = ff_cadd(0.5f, 0.0f, ff_mul(P, z));
    P = ff_cadd(1.0f, 0.0f, ff_mul(P, z));
    P = ff_cadd(1.0f, 0.0f, ff_mul(P, z));
    return P;
}

// sigmoid(y) correctly rounded to f32 (err ~1e-14 before final rounding)
__device__ __forceinline__ float sigmoid_rn(float y) {
    float z = fminf(fmaxf(-y, -30.0f), 30.0f);
    float n = rintf(z * 1.4426950408889634f);
    float rh = fmaf(-n, 0.693359375f, z);       // exact (9-bit constant)
    const double CRd = 0.69314718055994530942 - 0.693359375;
    ff p = ff_two_prod(-n, DFH(CRd));
    float s  = rh + p.h;
    float d  = s - rh;
    float e  = (rh - (s - d)) + (p.h - d);
    e += p.l + (-n) * DFL(CRd);
    float z2h = s + e;
    float z2l = (s - z2h) + e;
    ff E = ff_exp_core(z2h, z2l);
    int ni = (int)n;
    float sc = __int_as_float((ni + 127) << 23);
    float th = E.h * sc, tl = E.l * sc;
    float s2  = 1.0f + th;
    float d2  = s2 - 1.0f;
    float sl2 = (1.0f - (s2 - d2)) + (th - d2);
    sl2 += tl;
    float q0 = 1.0f / s2;
    float r  = fmaf(-q0, s2, 1.0f);
    r = fmaf(-q0, sl2, r);
    return fmaf(q0, r, q0);
}

// 2^e correctly rounded to f32 (e in ~(-6, 5))
__device__ __forceinline__ float exp2_rn(float e) {
    float n = rintf(e);
    float r = e - n;                     // exact
    const double LN2 = 0.69314718055994530942;
    float zh = r * DFH(LN2);
    float ze = fmaf(r, DFH(LN2), -zh);
    float zl = fmaf(r, DFL(LN2), ze);
    ff E = ff_exp_core(zh, zl);
    float pw = E.h + E.l;
    return pw * __int_as_float(((int)n + 127) << 23);
}

// ---------------------------------------------------------------------------
// Packed f32x2 helpers (FFMA2 — only reachable via PTX fma.rn.f32x2)
// ---------------------------------------------------------------------------
__device__ __forceinline__ unsigned long long pk2(float lo, float hi) {
    unsigned long long p;
    asm("mov.b64 %0, {%1, %2};" : "=l"(p) : "f"(lo), "f"(hi));
    return p;
}
__device__ __forceinline__ void upk2(unsigned long long p, float& lo, float& hi) {
    asm("mov.b64 {%0, %1}, %2;" : "=f"(lo), "=f"(hi) : "l"(p));
}
__device__ __forceinline__ unsigned long long fma2(unsigned long long a,
                                                   unsigned long long b,
                                                   unsigned long long c) {
    unsigned long long d;
    asm("fma.rn.f32x2 %0, %1, %2, %3;" : "=l"(d) : "l"(a), "l"(b), "l"(c));
    return d;
}
__device__ __forceinline__ unsigned long long add2(unsigned long long a,
                                                   unsigned long long b) {
    unsigned long long d;
    asm("add.rn.f32x2 %0, %1, %2;" : "=l"(d) : "l"(a), "l"(b));
    return d;
}

// ===========================================================================
// Fused prep: one block (256 thr) per (b,s).  All fp32-pipe (df64), no fp64.
//
// jax.image.resize 'linear' (x256): coord(i) = (i+0.5)/256 - 0.5.
//   region 0   : samples [0,128)          constant f[0]
//   region r   : samples [256r-128,+256)  lerp f[r-1]->f[r], frac=(2i+1)/512
//   region 250 : samples [63872,64000)    constant f[249]
// phi(k) = P_base + k*om_prev + k^2*q, recentred at kc = len/2.
// ===========================================================================
__global__ void __launch_bounds__(256) prep_kernel(const float* __restrict__ amps_in,
                                                   const float* __restrict__ freqs_in) {
    __shared__ float2 s_om[TT];
    __shared__ float  s_a[TT];
    __shared__ float2 s_wsum[8];

    int b = blockIdx.x / SS;
    int s = blockIdx.x % SS;
    int t = threadIdx.x;
    int lane = t & 31, warp = t >> 5;

    if (t < TT) {
        int gidx = (b*TT + t)*SS + s;

        float uf   = sigmoid_rn(freqs_in[gidx]);
        const float MIDI_MAX = 119.21309485364912f;   // np.float32(hz_to_midi(8000))
        float midi = uf * MIDI_MAX;
        float e    = (midi - 69.0f) / 12.0f;
        float pw   = exp2_rn(e);
        float freq = 440.0f * pw;

        float x  = amps_in[gidx];
        float sf = 1.0f / (1.0f + __expf(-x));
        float a  = 2.0f * __powf(sf, 2.3025850929940457f) + 1e-7f;
        if (freq >= 8000.0f) a = 0.0f;   // remove_above_nyquist

        const float CF = 3.9269908169872414e-4f;  // fp32(2*pi/16000)
        ff om = ff_two_prod(CF, freq);            // exact product
        s_om[t] = make_float2(om.h, om.l);
        s_a[t]  = a;
    }
    __syncthreads();

    // Segment increments: e_1 = 128*om_0; e_j = 128*(om_{j-2}+om_{j-1}).
    ff v = {0.0f, 0.0f};
    if (t == 1) {
        v = ff_scale({s_om[0].x, s_om[0].y}, 128.0f);
    } else if (t >= 2 && t <= 250) {
        ff a2 = ff_add({s_om[t-2].x, s_om[t-2].y}, {s_om[t-1].x, s_om[t-1].y});
        v = ff_scale(a2, 128.0f);
    }

    // Warp-level inclusive df64 scan (5 shfl steps).
    #pragma unroll
    for (int d = 1; d < 32; d <<= 1) {
        float oh = __shfl_up_sync(0xffffffffu, v.h, d);
        float ol = __shfl_up_sync(0xffffffffu, v.l, d);
        if (lane >= d) v = ff_add(v, {oh, ol});
    }
    if (lane == 31) s_wsum[warp] = make_float2(v.h, v.l);
    __syncthreads();
    // Add prefix of earlier warps' sums (<=7 df64 adds per thread).
    #pragma unroll
    for (int wprev = 0; wprev < 7; wprev++) {
        if (wprev < warp) {
            float2 ws = s_wsum[wprev];
            v = ff_add(v, {ws.x, ws.y});
        }
    }
    ff P = v;   // inclusive prefix: P_base of region t

    if (t <= 250) {
        ff base_df;
        float w, q, a0, da;
        if (t == 0) {
            ff om0 = {s_om[0].x, s_om[0].y};
            w = om0.h + om0.l; q = 0.0f;
            base_df = ff_scale(om0, 64.0f);
            a0 = s_a[0]; da = 0.0f;
        } else if (t == 250) {
            ff omN = {s_om[249].x, s_om[249].y};
            w = omN.h + omN.l; q = 0.0f;
            base_df = ff_add(P, ff_scale(omN, 64.0f));
            a0 = s_a[249]; da = 0.0f;
        } else {
            ff omp = {s_om[t-1].x, s_om[t-1].y};
            ff om  = {s_om[t].x,   s_om[t].y};
            ff qd  = ff_add(om, ff_neg(omp));
            q = (qd.h + qd.l) * (1.0f/512.0f);
            ff wv = ff_add(omp, om);
            w = 0.5f * (wv.h + wv.l);
            base_df = ff_add(P, ff_add(ff_mulf(omp, 96.0f), ff_scale(om, 32.0f)));
            a0 = s_a[t-1]; da = s_a[t] - s_a[t-1];
        }
        const double T2P = 6.2831853071795864769;
        float nn = rintf(base_df.h * 0.15915494309189535f);
        ff m = ff_two_prod(nn, DFH(T2P));
        m.l = fmaf(nn, DFL(T2P), m.l);
        ff bred = ff_add(base_df, ff_neg(m));
        float base = bred.h + bred.l;

        int idx = (b*NREG + t)*SS + s;
        g_p4[idx] = make_float4(w, q, base, a0);
        g_da[idx] = da;
    }
}

// ---------------------------------------------------------------------------
// Synthesis: one 128-thread block per region.  Harmonics split across the
// two 64-thread halves (hw=0: harmonics 0..31, hw=1: 32..63); 4 samples per
// thread as 2 packed f32x2 pairs; all 64 harmonics via MUFU.SIN (the
// measured floor).  Partial sums combined through smem.
// Best-measured configuration: 18.94us total / 13.0us synth.
// ---------------------------------------------------------------------------
__global__ void __launch_bounds__(128) synth_kernel(float* __restrict__ out) {
    __shared__ alignas(16) float sp[SS][12];  // [w,w][q,q][b,b][a0,a0][da,da][pad]
    __shared__ alignas(16) unsigned long long redA[64], redB[64];

    int b   = blockIdx.x / NREG;
    int r   = blockIdx.x % NREG;
    int tid = threadIdx.x;
    int ts  = tid & 63;          // sample group
    int hw  = tid >> 6;          // harmonic half (0 or 1)

    if (tid < SS) {
        int idx = (b*NREG + r)*SS + tid;
        float4 v = g_p4[idx];
        float  d = g_da[idx];
        sp[tid][0] = v.x; sp[tid][1] = v.x;
        sp[tid][2] = v.y; sp[tid][3] = v.y;
        sp[tid][4] = v.z; sp[tid][5] = v.z;
        sp[tid][6] = v.w; sp[tid][7] = v.w;
        sp[tid][8] = d;   sp[tid][9] = d;
    }
    __syncthreads();

    int n0, half;
    if (r == 0)        { n0 = 0;         half = 64;  }
    else if (r == 250) { n0 = 63872;     half = 64;  }
    else               { n0 = 256*r-128; half = 128; }
    bool full = (half == 128);

    // k' = (pos+1) - half  (recentred at segment midpoint)
    float kA0 = (float)(ts + 1 - half);
    float kA1 = (float)(ts + 1);
    float kB0 = (float)(ts + 65 - half);
    float kB1 = (float)(ts + 65);
    unsigned long long kpA = pk2(kA0, kA1);
    unsigned long long kpB = pk2(kB0, kB1);
    unsigned long long frA = pk2((float)(2*ts + 1)            * (1.0f/512.0f),
                                 (float)(2*(ts + half) + 1)   * (1.0f/512.0f));
    unsigned long long frB = pk2((float)(2*(ts+64) + 1)        * (1.0f/512.0f),
                                 (float)(2*(ts+64+half) + 1)   * (1.0f/512.0f));
    unsigned long long accA = 0ull, accB = 0ull;

    int sbeg = hw << 5;   // 0 or 32
    #pragma unroll
    for (int si = 0; si < 32; si++) {
        const unsigned long long* q8 = (const unsigned long long*)sp[sbeg + si];
        unsigned long long ww = q8[0];
        unsigned long long qq = q8[1];
        unsigned long long bb = q8[2];
        unsigned long long aa = q8[3];
        unsigned long long dd = q8[4];

        unsigned long long hA = fma2(kpA, qq, ww);
        unsigned long long tA = fma2(kpA, hA, bb);
        unsigned long long hB = fma2(kpB, qq, ww);
        unsigned long long tB = fma2(kpB, hB, bb);
        float tA0, tA1, tB0, tB1;
        upk2(tA, tA0, tA1);
        upk2(tB, tB0, tB1);
        float sA0 = __sinf(tA0);
        float sA1 = __sinf(tA1);
        float sB0 = __sinf(tB0);
        float sB1 = __sinf(tB1);
        unsigned long long svA = pk2(sA0, sA1);
        unsigned long long svB = pk2(sB0, sB1);
        unsigned long long amA = fma2(frA, dd, aa);
        unsigned long long amB = fma2(frB, dd, aa);
        accA = fma2(amA, svA, accA);
        accB = fma2(amB, svB, accB);
    }

    // Combine the two harmonic halves.
    if (hw == 1) {
        redA[ts] = accA;
        redB[ts] = accB;
    }
    __syncthreads();
    if (hw == 0) {
        accA = add2(accA, redA[ts]);
        accB = add2(accB, redB[ts]);
        float oA0, oA1, oB0, oB1;
        upk2(accA, oA0, oA1);
        upk2(accB, oB0, oB1);
        float* ob = out + (size_t)b*NSAMP + n0;
        ob[ts]        = oA0;
        ob[ts + half] = oA1;
        if (full) {
            ob[ts + 64]        = oB0;
            ob[ts + 64 + half] = oB1;
        }
    }
}

// ---------------------------------------------------------------------------
extern "C" void kernel_launch(void* const* d_in, const int* in_sizes, int n_in,
                              void* d_out, int out_size) {
    const float* amplitudes  = (const float*)d_in[0];
    const float* frequencies = (const float*)d_in[1];
    float* out = (float*)d_out;
    (void)in_sizes; (void)n_in; (void)out_size;

    prep_kernel<<<BB*SS, 256>>>(amplitudes, frequencies);
    synth_kernel<<<BB*NREG, 128>>>(out);
}

// round 16
// speedup vs baseline: 1.4349x; 1.0135x over previous
#include <cuda_runtime.h>
#include <math.h>

// Problem dims
#define BB 8
#define TT 250
#define SS 64
#define NSAMP 64000
#define NREG 251          // head(128) + 249 full segments(256) + tail(128)

// Scratch (no cudaMalloc allowed)
__device__ float4 g_p4[BB*NREG*SS];   // {w' (midpoint omega), q, base' (mod 2pi), a0}
__device__ float  g_da[BB*NREG*SS];   // amp delta

// ===========================================================================
// double-single (two-float) arithmetic on the fp32 pipe (exact-FMA based).
// ===========================================================================
struct ff { float h, l; };

__device__ __forceinline__ ff ff_two_prod(float a, float b) {
    float p = a * b;
    float e = fmaf(a, b, -p);
    return {p, e};
}
__device__ __forceinline__ ff ff_add(ff a, ff b) {
    float s  = a.h + b.h;
    float d  = s - a.h;
    float e  = (a.h - (s - d)) + (b.h - d);
    e += a.l + b.l;
    float h = s + e;
    float l = (s - h) + e;
    return {h, l};
}
__device__ __forceinline__ ff ff_neg(ff a) { return {-a.h, -a.l}; }
__device__ __forceinline__ ff ff_mul(ff a, ff z) {
    float p = a.h * z.h;
    float e = fmaf(a.h, z.h, -p);
    e = fmaf(a.h, z.l, e);
    e = fmaf(a.l, z.h, e);
    float h = p + e;
    float l = (p - h) + e;
    return {h, l};
}
__device__ __forceinline__ ff ff_cadd(float ch, float cl, ff p) {
    float s = ch + p.h;
    float e = (ch - s) + p.h;
    e += p.l + cl;
    float h = s + e;
    float l = (s - h) + e;
    return {h, l};
}
__device__ __forceinline__ ff ff_scale(ff a, float k) {   // k power of 2
    return {a.h * k, a.l * k};
}
__device__ __forceinline__ ff ff_mulf(ff a, float k) {    // general float k
    float p = k * a.h;
    float e = fmaf(k, a.h, -p);
    e = fmaf(k, a.l, e);
    float h = p + e;
    float l = (p - h) + e;
    return {h, l};
}

#define DFH(d) ((float)(d))
#define DFL(d) ((float)((d) - (double)(float)(d)))

// exp(z), |z| <= 0.3466, as two-float.  Taylor deg 11 (tail fp32).
__device__ __forceinline__ ff ff_exp_core(float zh, float zl) {
    float t;
    t = fmaf(zh, 2.5052108385441718775e-8f, 2.7557319223985890653e-7f);
    t = fmaf(zh, t, 2.7557319223985890653e-6f);
    t = fmaf(zh, t, 2.4801587301587301588e-5f);
    t = fmaf(zh, t, 1.9841269841269841270e-4f);
    ff P = {t, 0.0f};
    ff z = {zh, zl};
    P = ff_cadd(DFH(1.0/720.0), DFL(1.0/720.0), ff_mul(P, z));
    P = ff_cadd(DFH(1.0/120.0), DFL(1.0/120.0), ff_mul(P, z));
    P = ff_cadd(DFH(1.0/24.0),  DFL(1.0/24.0),  ff_mul(P, z));
    P = ff_cadd(DFH(1.0/6.0),   DFL(1.0/6.0),   ff_mul(P, z));
    P = ff_cadd(0.5f, 0.0f, ff_mul(P, z));
    P = ff_cadd(1.0f, 0.0f, ff_mul(P, z));
    P = ff_cadd(1.0f, 0.0f, ff_mul(P, z));
    return P;
}

// sigmoid(y) correctly rounded to f32 (err ~1e-14 before final rounding)
__device__ __forceinline__ float sigmoid_rn(float y) {
    float z = fminf(fmaxf(-y, -30.0f), 30.0f);
    float n = rintf(z * 1.4426950408889634f);
    float rh = fmaf(-n, 0.693359375f, z);       // exact (9-bit constant)
    const double CRd = 0.69314718055994530942 - 0.693359375;
    ff p = ff_two_prod(-n, DFH(CRd));
    float s  = rh + p.h;
    float d  = s - rh;
    float e  = (rh - (s - d)) + (p.h - d);
    e += p.l + (-n) * DFL(CRd);
    float z2h = s + e;
    float z2l = (s - z2h) + e;
    ff E = ff_exp_core(z2h, z2l);
    int ni = (int)n;
    float sc = __int_as_float((ni + 127) << 23);
    float th = E.h * sc, tl = E.l * sc;
    float s2  = 1.0f + th;
    float d2  = s2 - 1.0f;
    float sl2 = (1.0f - (s2 - d2)) + (th - d2);
    sl2 += tl;
    float q0 = 1.0f / s2;
    float r  = fmaf(-q0, s2, 1.0f);
    r = fmaf(-q0, sl2, r);
    return fmaf(q0, r, q0);
}

// 2^e correctly rounded to f32 (e in ~(-6, 5))
__device__ __forceinline__ float exp2_rn(float e) {
    float n = rintf(e);
    float r = e - n;                     // exact
    const double LN2 = 0.69314718055994530942;
    float zh = r * DFH(LN2);
    float ze = fmaf(r, DFH(LN2), -zh);
    float zl = fmaf(r, DFL(LN2), ze);
    ff E = ff_exp_core(zh, zl);
    float pw = E.h + E.l;
    return pw * __int_as_float(((int)n + 127) << 23);
}

// ---------------------------------------------------------------------------
// Packed f32x2 helpers (FFMA2 — only reachable via PTX fma.rn.f32x2)
// ---------------------------------------------------------------------------
__device__ __forceinline__ unsigned long long pk2(float lo, float hi) {
    unsigned long long p;
    asm("mov.b64 %0, {%1, %2};" : "=l"(p) : "f"(lo), "f"(hi));
    return p;
}
__device__ __forceinline__ void upk2(unsigned long long p, float& lo, float& hi) {
    asm("mov.b64 {%0, %1}, %2;" : "=f"(lo), "=f"(hi) : "l"(p));
}
__device__ __forceinline__ unsigned long long fma2(unsigned long long a,
                                                   unsigned long long b,
                                                   unsigned long long c) {
    unsigned long long d;
    asm("fma.rn.f32x2 %0, %1, %2, %3;" : "=l"(d) : "l"(a), "l"(b), "l"(c));
    return d;
}
__device__ __forceinline__ unsigned long long add2(unsigned long long a,
                                                   unsigned long long b) {
    unsigned long long d;
    asm("add.rn.f32x2 %0, %1, %2;" : "=l"(d) : "l"(a), "l"(b));
    return d;
}

// ===========================================================================
// Fused prep: one block (256 thr) per (b,s).  All fp32-pipe (df64), no fp64.
//
// jax.image.resize 'linear' (x256): coord(i) = (i+0.5)/256 - 0.5.
//   region 0   : samples [0,128)          constant f[0]
//   region r   : samples [256r-128,+256)  lerp f[r-1]->f[r], frac=(2i+1)/512
//   region 250 : samples [63872,64000)    constant f[249]
// phi(k) = P_base + k*om_prev + k^2*q, recentred at kc = len/2.
// ===========================================================================
__global__ void __launch_bounds__(256) prep_kernel(const float* __restrict__ amps_in,
                                                   const float* __restrict__ freqs_in) {
    __shared__ float2 s_om[TT];
    __shared__ float  s_a[TT];
    __shared__ float2 s_wsum[8];

    int b = blockIdx.x / SS;
    int s = blockIdx.x % SS;
    int t = threadIdx.x;
    int lane = t & 31, warp = t >> 5;

    if (t < TT) {
        int gidx = (b*TT + t)*SS + s;

        float uf   = sigmoid_rn(freqs_in[gidx]);
        const float MIDI_MAX = 119.21309485364912f;   // np.float32(hz_to_midi(8000))
        float midi = uf * MIDI_MAX;
        float e    = (midi - 69.0f) / 12.0f;
        float pw   = exp2_rn(e);
        float freq = 440.0f * pw;

        float x  = amps_in[gidx];
        float sf = 1.0f / (1.0f + __expf(-x));
        float a  = 2.0f * __powf(sf, 2.3025850929940457f) + 1e-7f;
        if (freq >= 8000.0f) a = 0.0f;   // remove_above_nyquist

        const float CF = 3.9269908169872414e-4f;  // fp32(2*pi/16000)
        ff om = ff_two_prod(CF, freq);            // exact product
        s_om[t] = make_float2(om.h, om.l);
        s_a[t]  = a;
    }
    __syncthreads();

    // Segment increments: e_1 = 128*om_0; e_j = 128*(om_{j-2}+om_{j-1}).
    ff v = {0.0f, 0.0f};
    if (t == 1) {
        v = ff_scale({s_om[0].x, s_om[0].y}, 128.0f);
    } else if (t >= 2 && t <= 250) {
        ff a2 = ff_add({s_om[t-2].x, s_om[t-2].y}, {s_om[t-1].x, s_om[t-1].y});
        v = ff_scale(a2, 128.0f);
    }

    // Warp-level inclusive df64 scan (5 shfl steps).
    #pragma unroll
    for (int d = 1; d < 32; d <<= 1) {
        float oh = __shfl_up_sync(0xffffffffu, v.h, d);
        float ol = __shfl_up_sync(0xffffffffu, v.l, d);
        if (lane >= d) v = ff_add(v, {oh, ol});
    }
    if (lane == 31) s_wsum[warp] = make_float2(v.h, v.l);
    __syncthreads();
    // Add prefix of earlier warps' sums (<=7 df64 adds per thread).
    #pragma unroll
    for (int wprev = 0; wprev < 7; wprev++) {
        if (wprev < warp) {
            float2 ws = s_wsum[wprev];
            v = ff_add(v, {ws.x, ws.y});
        }
    }
    ff P = v;   // inclusive prefix: P_base of region t

    if (t <= 250) {
        ff base_df;
        float w, q, a0, da;
        if (t == 0) {
            ff om0 = {s_om[0].x, s_om[0].y};
            w = om0.h + om0.l; q = 0.0f;
            base_df = ff_scale(om0, 64.0f);
            a0 = s_a[0]; da = 0.0f;
        } else if (t == 250) {
            ff omN = {s_om[249].x, s_om[249].y};
            w = omN.h + omN.l; q = 0.0f;
            base_df = ff_add(P, ff_scale(omN, 64.0f));
            a0 = s_a[249]; da = 0.0f;
        } else {
            ff omp = {s_om[t-1].x, s_om[t-1].y};
            ff om  = {s_om[t].x,   s_om[t].y};
            ff qd  = ff_add(om, ff_neg(omp));
            q = (qd.h + qd.l) * (1.0f/512.0f);
            ff wv = ff_add(omp, om);
            w = 0.5f * (wv.h + wv.l);
            base_df = ff_add(P, ff_add(ff_mulf(omp, 96.0f), ff_scale(om, 32.0f)));
            a0 = s_a[t-1]; da = s_a[t] - s_a[t-1];
        }
        const double T2P = 6.2831853071795864769;
        float nn = rintf(base_df.h * 0.15915494309189535f);
        ff m = ff_two_prod(nn, DFH(T2P));
        m.l = fmaf(nn, DFL(T2P), m.l);
        ff bred = ff_add(base_df, ff_neg(m));
        float base = bred.h + bred.l;

        int idx = (b*NREG + t)*SS + s;
        g_p4[idx] = make_float4(w, q, base, a0);
        g_da[idx] = da;
    }
}

// ---------------------------------------------------------------------------
// Synthesis: one 128-thread block per region.  Harmonics split across the
// two 64-thread halves (hw=0: harmonics 0..31, hw=1: 32..63); 4 samples per
// thread as 2 packed f32x2 pairs; all 64 harmonics via MUFU.SIN (the
// measured hardware floor for this workload).  Partial sums via smem.
// ---------------------------------------------------------------------------
__global__ void __launch_bounds__(128) synth_kernel(float* __restrict__ out) {
    __shared__ alignas(16) float sp[SS][12];  // [w,w][q,q][b,b][a0,a0][da,da][pad]
    __shared__ alignas(16) unsigned long long redA[64], redB[64];

    int b   = blockIdx.x / NREG;
    int r   = blockIdx.x % NREG;
    int tid = threadIdx.x;
    int ts  = tid & 63;          // sample group
    int hw  = tid >> 6;          // harmonic half (0 or 1)

    if (tid < SS) {
        int idx = (b*NREG + r)*SS + tid;
        float4 v = g_p4[idx];
        float  d = g_da[idx];
        sp[tid][0] = v.x; sp[tid][1] = v.x;
        sp[tid][2] = v.y; sp[tid][3] = v.y;
        sp[tid][4] = v.z; sp[tid][5] = v.z;
        sp[tid][6] = v.w; sp[tid][7] = v.w;
        sp[tid][8] = d;   sp[tid][9] = d;
    }
    __syncthreads();

    int n0, half;
    if (r == 0)        { n0 = 0;         half = 64;  }
    else if (r == 250) { n0 = 63872;     half = 64;  }
    else               { n0 = 256*r-128; half = 128; }
    bool full = (half == 128);

    // k' = (pos+1) - half  (recentred at segment midpoint)
    float kA0 = (float)(ts + 1 - half);
    float kA1 = (float)(ts + 1);
    float kB0 = (float)(ts + 65 - half);
    float kB1 = (float)(ts + 65);
    unsigned long long kpA = pk2(kA0, kA1);
    unsigned long long kpB = pk2(kB0, kB1);
    unsigned long long frA = pk2((float)(2*ts + 1)            * (1.0f/512.0f),
                                 (float)(2*(ts + half) + 1)   * (1.0f/512.0f));
    unsigned long long frB = pk2((float)(2*(ts+64) + 1)        * (1.0f/512.0f),
                                 (float)(2*(ts+64+half) + 1)   * (1.0f/512.0f));
    unsigned long long accA = 0ull, accB = 0ull;

    int sbeg = hw << 5;   // 0 or 32
    #pragma unroll
    for (int si = 0; si < 32; si++) {
        const unsigned long long* q8 = (const unsigned long long*)sp[sbeg + si];
        unsigned long long ww = q8[0];
        unsigned long long qq = q8[1];
        unsigned long long bb = q8[2];
        unsigned long long aa = q8[3];
        unsigned long long dd = q8[4];

        unsigned long long hA = fma2(kpA, qq, ww);
        unsigned long long tA = fma2(kpA, hA, bb);
        unsigned long long hB = fma2(kpB, qq, ww);
        unsigned long long tB = fma2(kpB, hB, bb);
        float tA0, tA1, tB0, tB1;
        upk2(tA, tA0, tA1);
        upk2(tB, tB0, tB1);
        float sA0 = __sinf(tA0);
        float sA1 = __sinf(tA1);
        float sB0 = __sinf(tB0);
        float sB1 = __sinf(tB1);
        unsigned long long svA = pk2(sA0, sA1);
        unsigned long long svB = pk2(sB0, sB1);
        unsigned long long amA = fma2(frA, dd, aa);
        unsigned long long amB = fma2(frB, dd, aa);
        accA = fma2(amA, svA, accA);
        accB = fma2(amB, svB, accB);
    }

    // Combine the two harmonic halves.
    if (hw == 1) {
        redA[ts] = accA;
        redB[ts] = accB;
    }
    __syncthreads();
    if (hw == 0) {
        accA = add2(accA, redA[ts]);
        accB = add2(accB, redB[ts]);
        float oA0, oA1, oB0, oB1;
        upk2(accA, oA0, oA1);
        upk2(accB, oB0, oB1);
        float* ob = out + (size_t)b*NSAMP + n0;
        ob[ts]        = oA0;
        ob[ts + half] = oA1;
        if (full) {
            ob[ts + 64]        = oB0;
            ob[ts + 64 + half] = oB1;
        }
    }
}

// ---------------------------------------------------------------------------
extern "C" void kernel_launch(void* const* d_in, const int* in_sizes, int n_in,
                              void* d_out, int out_size) {
    const float* amplitudes  = (const float*)d_in[0];
    const float* frequencies = (const float*)d_in[1];
    float* out = (float*)d_out;
    (void)in_sizes; (void)n_in; (void)out_size;

    prep_kernel<<<BB*SS, 256>>>(amplitudes, frequencies);
    synth_kernel<<<BB*NREG, 128>>>(out);
}